// round 10
// baseline (speedup 1.0000x reference)
#include <cuda_runtime.h>
#include <cstdint>

#define N_NODES 8192
#define N_COMM 16
#define DIMS 64

#define TILE_ROWS 64
#define TILE_COLS 512
#define N_TILES_R (N_NODES / TILE_ROWS)   // 128
#define N_TILES_C (N_NODES / TILE_COLS)   // 16
#define N_TILES (N_TILES_R * N_TILES_C)   // 2048
#define S2_GRID 592                        // 148 SMs * 4 blocks launched

// Scratch (no device allocation allowed) — fully rewritten every launch.
__device__ float g_pi[N_NODES * N_COMM];
__device__ __align__(16) float g_partI[N_TILES];
__device__ __align__(16) float g_partR[N_TILES];
__device__ int g_ticket;
__device__ int g_done;

// ---- packed f32x2 helpers (sm_103a; ptxas never emits these from C++) ----
__device__ __forceinline__ unsigned long long fma2(unsigned long long a,
                                                   unsigned long long b,
                                                   unsigned long long c) {
    unsigned long long d;
    asm("fma.rn.f32x2 %0, %1, %2, %3;" : "=l"(d) : "l"(a), "l"(b), "l"(c));
    return d;
}
__device__ __forceinline__ unsigned long long add2(unsigned long long a,
                                                   unsigned long long b) {
    unsigned long long d;
    asm("add.rn.f32x2 %0, %1, %2;" : "=l"(d) : "l"(a), "l"(b));
    return d;
}
__device__ __forceinline__ unsigned long long pack2(float x, float y) {
    unsigned long long r;
    asm("mov.b64 %0, {%1, %2};" : "=l"(r) : "f"(x), "f"(y));
    return r;
}
__device__ __forceinline__ float2 unpack2(unsigned long long v) {
    float2 f;
    asm("mov.b64 {%0, %1}, %2;" : "=f"(f.x), "=f"(f.y) : "l"(v));
    return f;
}

// ============================================================================
// Stage 1: distances over 3 manifolds -> dist_norm -> softmax -> g_pi
// (unchanged from R6 — measured ~5us). Also resets stage2 counters.
// ============================================================================
__global__ __launch_bounds__(256) void stage1(const float* __restrict__ ne,
                                              const float* __restrict__ comm) {
    __shared__ float sC[N_COMM * 68];            // [k][d], row padded to 68
    __shared__ float sX[16][3 * DIMS + 4];       // [node][l*64+d]
    int tid = threadIdx.x;

    if (blockIdx.x == 0 && tid == 0) { g_ticket = 0; g_done = 0; }

    for (int e = tid; e < N_COMM * DIMS; e += 256) {
        int k = e >> 6, d = e & 63;
        sC[k * 68 + d] = comm[e];
    }
    int n0 = blockIdx.x * 16;
#pragma unroll
    for (int l = 0; l < 3; ++l) {
        float4 v = *(const float4*)(ne + ((size_t)l * N_NODES + n0) * DIMS + tid * 4);
        int node = tid >> 4;
        int d = (tid & 15) * 4;
        *(float4*)&sX[node][l * DIMS + d] = v;
    }
    __syncthreads();

    int warp = tid >> 5, lane = tid & 31;
    int half = lane >> 4, k = lane & 15;
    int nl = warp * 2 + half;
    int node = n0 + nl;

    const float4* xE = (const float4*)&sX[nl][0];
    const float4* xL = (const float4*)&sX[nl][DIMS];
    const float4* xS = (const float4*)&sX[nl][2 * DIMS];
    const float4* cB = (const float4*)&sC[k * 68];

    float t0 = sX[nl][DIMS] * sC[k * 68];
    float accE = 0.f, acc1 = 0.f, acc2 = 0.f;
#pragma unroll
    for (int d4 = 0; d4 < DIMS / 4; ++d4) {
        float4 c = cB[d4];
        float4 a0 = xE[d4], a1 = xL[d4], a2 = xS[d4];
        float dx = a0.x - c.x, dy = a0.y - c.y, dz = a0.z - c.z, dw = a0.w - c.w;
        accE = fmaf(dx, dx, accE); accE = fmaf(dy, dy, accE);
        accE = fmaf(dz, dz, accE); accE = fmaf(dw, dw, accE);
        acc1 = fmaf(a1.x, c.x, acc1); acc1 = fmaf(a1.y, c.y, acc1);
        acc1 = fmaf(a1.z, c.z, acc1); acc1 = fmaf(a1.w, c.w, acc1);
        acc2 = fmaf(a2.x, c.x, acc2); acc2 = fmaf(a2.y, c.y, acc2);
        acc2 = fmaf(a2.z, c.z, acc2); acc2 = fmaf(a2.w, c.w, acc2);
    }
    float lip = acc1 - 2.f * t0;
    float arg = fmaxf(-lip, 1.0000001f);
    float dl = acoshf(arg);
    float cs = fminf(fmaxf(acc2, -0.9999999f), 0.9999999f);
    float ds = acosf(cs);
    float dn = sqrtf(accE + dl * dl + ds * ds);

    float m = dn;
#pragma unroll
    for (int o = 8; o; o >>= 1) m = fmaxf(m, __shfl_xor_sync(0xffffffffu, m, o, 16));
    float e = expf(dn - m);
    float s = e;
#pragma unroll
    for (int o = 8; o; o >>= 1) s += __shfl_xor_sync(0xffffffffu, s, o, 16);

    g_pi[node * N_COMM + k] = e / s;
}

// ============================================================================
// Stage 2: streaming pass over ricci, work-stealing over 2048 tiles (64x512).
// Dot-form with lane-packed columns:
//   pjx[m] = (pi_j0[m], pi_j1[m])   register-resident (16 x f32x2)
//   sDup[i][m] = (pi_i[m], pi_i[m]) duplicated in smem (broadcast LDS.128)
//   t (packed) = (dot_j0, dot_j1) via two 8-deep split chains
//   fold: acc = fma2(rv, t_a + t_b, acc)  -- zero pack/mov per row
// NO launch_bounds min-blocks cap: R6's regs=64 cap caused spills (L1 65.7%).
// ============================================================================
__global__ __launch_bounds__(256) void stage2(const float* __restrict__ R,
                                              const float* __restrict__ alpha,
                                              float* __restrict__ out) {
    __shared__ __align__(16) unsigned long long sDup[TILE_ROWS * N_COMM]; // 8 KB
    __shared__ float redI[8], redR[8];
    __shared__ int s_tile;
    __shared__ int s_last;

    int tid = threadIdx.x;
    int warp = tid >> 5, lane = tid & 31;
    const unsigned long long* gp = (const unsigned long long*)g_pi;

    for (;;) {
        if (tid == 0) s_tile = atomicAdd(&g_ticket, 1);
        __syncthreads();                                      // A
        int t = s_tile;
        if (t >= N_TILES) break;
        int it = t & (N_TILES_R - 1);                         // row-fastest
        int jt = t >> 7;                                      // consecutive tickets share jt
        int i0 = it * TILE_ROWS;
        int jb = jt * TILE_COLS + warp * 64 + lane * 2;

        // stage duplicated pi rows [i0, i0+64) into shared: sDup[e] = (v, v)
        for (int e = tid; e < TILE_ROWS * N_COMM; e += 256) {
            float v = g_pi[i0 * N_COMM + e];
            sDup[e] = pack2(v, v);
        }
        __syncthreads();                                      // B

        // lane's two columns, interleaved: pjx[m] = (pi_j0[m], pi_j1[m])
        unsigned long long pjx[16];
#pragma unroll
        for (int m = 0; m < 8; ++m) {
            float2 a = unpack2(gp[(size_t)jb * 8 + m]);
            float2 b = unpack2(gp[(size_t)(jb + 1) * 8 + m]);
            pjx[2 * m]     = pack2(a.x, b.x);
            pjx[2 * m + 1] = pack2(a.y, b.y);
        }

        const unsigned long long* Rp =
            (const unsigned long long*)(R + (size_t)i0 * N_NODES + jb);
        const ulonglong2* sq = (const ulonglong2*)sDup;

        unsigned long long accI2 = 0ull;
        unsigned long long accR2 = 0ull;

#pragma unroll 4
        for (int i = 0; i < TILE_ROWS; ++i) {
            unsigned long long rv = __ldg(Rp + (size_t)i * (N_NODES / 2));
            const ulonglong2* q = sq + i * 8;
            unsigned long long t_a = 0ull, t_b = 0ull;        // 2 split chains
#pragma unroll
            for (int m2 = 0; m2 < 8; ++m2) {
                ulonglong2 qv = q[m2];                        // broadcast LDS.128
                t_a = fma2(qv.x, pjx[2 * m2], t_a);
                t_b = fma2(qv.y, pjx[2 * m2 + 1], t_b);
            }
            accI2 = fma2(rv, add2(t_a, t_b), accI2);          // (dot_j0, dot_j1)
            accR2 = add2(accR2, rv);
        }

        float2 ai = unpack2(accI2); float aI = ai.x + ai.y;
        float2 ar = unpack2(accR2); float aR = ar.x + ar.y;
#pragma unroll
        for (int o = 16; o; o >>= 1) {
            aI += __shfl_xor_sync(0xffffffffu, aI, o);
            aR += __shfl_xor_sync(0xffffffffu, aR, o);
        }
        if (lane == 0) { redI[warp] = aI; redR[warp] = aR; }
        __syncthreads();                                      // C
        if (tid == 0) {
            float sI = 0.f, sR = 0.f;
#pragma unroll
            for (int w = 0; w < 8; ++w) { sI += redI[w]; sR += redR[w]; }
            g_partI[t] = sI;
            g_partR[t] = sR;
            __threadfence();
            int d = atomicAdd(&g_done, 1);
            s_last = (d == N_TILES - 1);
        }
        __syncthreads();                                      // D
        if (s_last) {
            // last block: deterministic fixed-order reduce of all tile partials
            __threadfence();
            const float4* pI = (const float4*)g_partI;
            const float4* pR = (const float4*)g_partR;
            float aI2 = 0.f, aR2 = 0.f;
            for (int b = tid; b < N_TILES / 4; b += 256) {
                float4 vi = pI[b], vr = pR[b];
                aI2 += (vi.x + vi.y) + (vi.z + vi.w);
                aR2 += (vr.x + vr.y) + (vr.z + vr.w);
            }
#pragma unroll
            for (int o = 16; o; o >>= 1) {
                aI2 += __shfl_xor_sync(0xffffffffu, aI2, o);
                aR2 += __shfl_xor_sync(0xffffffffu, aR2, o);
            }
            if (lane == 0) { redI[warp] = aI2; redR[warp] = aR2; }
            __syncthreads();                                  // E
            if (tid == 0) {
                float sI = 0.f, sR = 0.f;
#pragma unroll
                for (int w = 0; w < 8; ++w) { sI += redI[w]; sR += redR[w]; }
                // K*N = 131072 ; K*K*N = 2097152
                out[0] = alpha[0] * (sI / 131072.0f) - sR / 2097152.0f;
            }
        }
    }
}

extern "C" void kernel_launch(void* const* d_in, const int* in_sizes, int n_in,
                              void* d_out, int out_size) {
    const float* ne    = (const float*)d_in[0];  // (3, 8192, 64) f32
    const float* comm  = (const float*)d_in[1];  // (16, 64) f32
    const float* ricci = (const float*)d_in[2];  // (8192, 8192) f32
    const float* alpha = (const float*)d_in[3];  // scalar f32
    float* out = (float*)d_out;                  // 1 element f32

    stage1<<<N_NODES / 16, 256>>>(ne, comm);
    stage2<<<S2_GRID, 256>>>(ricci, alpha, out);
}

// round 11
// speedup vs baseline: 1.0681x; 1.0681x over previous
#include <cuda_runtime.h>
#include <cstdint>

#define N_NODES 8192
#define N_COMM 16
#define DIMS 64

#define TILE_ROWS 64
#define TILE_COLS 1024
#define N_TILES_R (N_NODES / TILE_ROWS)   // 128
#define N_TILES_C (N_NODES / TILE_COLS)   // 8
#define N_TILES (N_TILES_R * N_TILES_C)   // 1024
#define S2_GRID 296                        // 148 SMs * 2 resident blocks

// Scratch (no device allocation allowed) — fully rewritten every launch.
__device__ float g_pi[N_NODES * N_COMM];
__device__ __align__(16) float g_partI[N_TILES];
__device__ __align__(16) float g_partR[N_TILES];
__device__ int g_ticket;
__device__ int g_done;

typedef unsigned long long ull;

// ---- packed f32x2 helpers (sm_103a; ptxas never emits these from C++) ----
__device__ __forceinline__ ull fma2(ull a, ull b, ull c) {
    ull d;
    asm("fma.rn.f32x2 %0, %1, %2, %3;" : "=l"(d) : "l"(a), "l"(b), "l"(c));
    return d;
}
__device__ __forceinline__ ull add2(ull a, ull b) {
    ull d;
    asm("add.rn.f32x2 %0, %1, %2;" : "=l"(d) : "l"(a), "l"(b));
    return d;
}
__device__ __forceinline__ ull pack2(float x, float y) {
    ull r;
    asm("mov.b64 %0, {%1, %2};" : "=l"(r) : "f"(x), "f"(y));
    return r;
}
__device__ __forceinline__ float2 unpack2(ull v) {
    float2 f;
    asm("mov.b64 {%0, %1}, %2;" : "=f"(f.x), "=f"(f.y) : "l"(v));
    return f;
}

// ============================================================================
// Stage 1: distances over 3 manifolds -> dist_norm -> softmax -> g_pi
// (unchanged — measured ~5us). Also resets stage2 counters.
// ============================================================================
__global__ __launch_bounds__(256) void stage1(const float* __restrict__ ne,
                                              const float* __restrict__ comm) {
    __shared__ float sC[N_COMM * 68];            // [k][d], row padded to 68
    __shared__ float sX[16][3 * DIMS + 4];       // [node][l*64+d]
    int tid = threadIdx.x;

    if (blockIdx.x == 0 && tid == 0) { g_ticket = 0; g_done = 0; }

    for (int e = tid; e < N_COMM * DIMS; e += 256) {
        int k = e >> 6, d = e & 63;
        sC[k * 68 + d] = comm[e];
    }
    int n0 = blockIdx.x * 16;
#pragma unroll
    for (int l = 0; l < 3; ++l) {
        float4 v = *(const float4*)(ne + ((size_t)l * N_NODES + n0) * DIMS + tid * 4);
        int node = tid >> 4;
        int d = (tid & 15) * 4;
        *(float4*)&sX[node][l * DIMS + d] = v;
    }
    __syncthreads();

    int warp = tid >> 5, lane = tid & 31;
    int half = lane >> 4, k = lane & 15;
    int nl = warp * 2 + half;
    int node = n0 + nl;

    const float4* xE = (const float4*)&sX[nl][0];
    const float4* xL = (const float4*)&sX[nl][DIMS];
    const float4* xS = (const float4*)&sX[nl][2 * DIMS];
    const float4* cB = (const float4*)&sC[k * 68];

    float t0 = sX[nl][DIMS] * sC[k * 68];
    float accE = 0.f, acc1 = 0.f, acc2 = 0.f;
#pragma unroll
    for (int d4 = 0; d4 < DIMS / 4; ++d4) {
        float4 c = cB[d4];
        float4 a0 = xE[d4], a1 = xL[d4], a2 = xS[d4];
        float dx = a0.x - c.x, dy = a0.y - c.y, dz = a0.z - c.z, dw = a0.w - c.w;
        accE = fmaf(dx, dx, accE); accE = fmaf(dy, dy, accE);
        accE = fmaf(dz, dz, accE); accE = fmaf(dw, dw, accE);
        acc1 = fmaf(a1.x, c.x, acc1); acc1 = fmaf(a1.y, c.y, acc1);
        acc1 = fmaf(a1.z, c.z, acc1); acc1 = fmaf(a1.w, c.w, acc1);
        acc2 = fmaf(a2.x, c.x, acc2); acc2 = fmaf(a2.y, c.y, acc2);
        acc2 = fmaf(a2.z, c.z, acc2); acc2 = fmaf(a2.w, c.w, acc2);
    }
    float lip = acc1 - 2.f * t0;
    float arg = fmaxf(-lip, 1.0000001f);
    float dl = acoshf(arg);
    float cs = fminf(fmaxf(acc2, -0.9999999f), 0.9999999f);
    float ds = acosf(cs);
    float dn = sqrtf(accE + dl * dl + ds * ds);

    float m = dn;
#pragma unroll
    for (int o = 8; o; o >>= 1) m = fmaxf(m, __shfl_xor_sync(0xffffffffu, m, o, 16));
    float e = expf(dn - m);
    float s = e;
#pragma unroll
    for (int o = 8; o; o >>= 1) s += __shfl_xor_sync(0xffffffffu, s, o, 16);

    g_pi[node * N_COMM + k] = e / s;
}

// ============================================================================
// Stage 2: streaming pass over ricci, work-stealing over 1024 tiles (64x1024).
// Lane owns FOUR j-columns:
//   p01[m] = (pi_j0[m], pi_j1[m]), p23[m] = (pi_j2[m], pi_j3[m])  (64 regs)
//   sDup[i][m] = (pi_i[m], pi_i[m]) duplicated in smem (broadcast LDS.128)
//   4 independent 8-deep fma2 chains; R via one LDG.128 whose two reg-pairs
//   (r0,r1),(r2,r3) feed the folds directly — zero pack/mov per row.
// __launch_bounds__(256,2): 128-reg budget. R6/R10 regression root cause was
// ptxas targeting 64 regs and SPILLING (regs=64 + L1~62-66% both rounds).
// ============================================================================
__global__ __launch_bounds__(256, 2) void stage2(const float* __restrict__ R,
                                                 const float* __restrict__ alpha,
                                                 float* __restrict__ out) {
    __shared__ __align__(16) ull sDup[TILE_ROWS * N_COMM];    // 8 KB
    __shared__ float redI[8], redR[8];
    __shared__ int s_tile;
    __shared__ int s_last;

    int tid = threadIdx.x;
    int warp = tid >> 5, lane = tid & 31;
    const ull* gp = (const ull*)g_pi;

    for (;;) {
        if (tid == 0) s_tile = atomicAdd(&g_ticket, 1);
        __syncthreads();                                      // A
        int t = s_tile;
        if (t >= N_TILES) break;
        int it = t & (N_TILES_R - 1);                         // row-fastest
        int jt = t >> 7;                                      // tickets share jt
        int i0 = it * TILE_ROWS;
        int jb = jt * TILE_COLS + warp * 128 + lane * 4;

        // stage duplicated pi rows [i0, i0+64): sDup[e] = (v, v)
        for (int e = tid; e < TILE_ROWS * N_COMM; e += 256) {
            float v = g_pi[i0 * N_COMM + e];
            sDup[e] = pack2(v, v);
        }
        __syncthreads();                                      // B

        // lane's four columns, column-pair interleaved
        ull p01[16], p23[16];
#pragma unroll
        for (int m = 0; m < 8; ++m) {
            float2 c0 = unpack2(gp[(size_t)(jb + 0) * 8 + m]);
            float2 c1 = unpack2(gp[(size_t)(jb + 1) * 8 + m]);
            float2 c2 = unpack2(gp[(size_t)(jb + 2) * 8 + m]);
            float2 c3 = unpack2(gp[(size_t)(jb + 3) * 8 + m]);
            p01[2 * m]     = pack2(c0.x, c1.x);
            p01[2 * m + 1] = pack2(c0.y, c1.y);
            p23[2 * m]     = pack2(c2.x, c3.x);
            p23[2 * m + 1] = pack2(c2.y, c3.y);
        }

        const ulonglong2* __restrict__ Rp =
            (const ulonglong2*)(R + (size_t)i0 * N_NODES + jb);
        const ulonglong2* sq = (const ulonglong2*)sDup;

        ull accI = 0ull, accR = 0ull;

#pragma unroll 2
        for (int i = 0; i < TILE_ROWS; ++i) {
            ulonglong2 rv = Rp[(size_t)i * (N_NODES / 4)];    // LDG.128: 4 R values
            const ulonglong2* q = sq + i * 8;
            ull ta01 = 0ull, tb01 = 0ull, ta23 = 0ull, tb23 = 0ull;
#pragma unroll
            for (int m2 = 0; m2 < 8; ++m2) {
                ulonglong2 qv = q[m2];                        // broadcast LDS.128
                ta01 = fma2(qv.x, p01[2 * m2], ta01);
                tb01 = fma2(qv.y, p01[2 * m2 + 1], tb01);
                ta23 = fma2(qv.x, p23[2 * m2], ta23);
                tb23 = fma2(qv.y, p23[2 * m2 + 1], tb23);
            }
            accI = fma2(rv.x, add2(ta01, tb01), accI);        // (dot_j0, dot_j1)
            accI = fma2(rv.y, add2(ta23, tb23), accI);        // (dot_j2, dot_j3)
            accR = add2(accR, add2(rv.x, rv.y));
        }

        float2 ai = unpack2(accI); float aI = ai.x + ai.y;
        float2 ar = unpack2(accR); float aR = ar.x + ar.y;
#pragma unroll
        for (int o = 16; o; o >>= 1) {
            aI += __shfl_xor_sync(0xffffffffu, aI, o);
            aR += __shfl_xor_sync(0xffffffffu, aR, o);
        }
        if (lane == 0) { redI[warp] = aI; redR[warp] = aR; }
        __syncthreads();                                      // C
        if (tid == 0) {
            float sI = 0.f, sR = 0.f;
#pragma unroll
            for (int w = 0; w < 8; ++w) { sI += redI[w]; sR += redR[w]; }
            g_partI[t] = sI;
            g_partR[t] = sR;
            __threadfence();
            int d = atomicAdd(&g_done, 1);
            s_last = (d == N_TILES - 1);
        }
        __syncthreads();                                      // D
        if (s_last) {
            // last block: deterministic fixed-order reduce of all tile partials
            __threadfence();
            const float4* pI = (const float4*)g_partI;
            const float4* pR = (const float4*)g_partR;
            float aI2 = 0.f, aR2 = 0.f;
            for (int b = tid; b < N_TILES / 4; b += 256) {
                float4 vi = pI[b], vr = pR[b];
                aI2 += (vi.x + vi.y) + (vi.z + vi.w);
                aR2 += (vr.x + vr.y) + (vr.z + vr.w);
            }
#pragma unroll
            for (int o = 16; o; o >>= 1) {
                aI2 += __shfl_xor_sync(0xffffffffu, aI2, o);
                aR2 += __shfl_xor_sync(0xffffffffu, aR2, o);
            }
            if (lane == 0) { redI[warp] = aI2; redR[warp] = aR2; }
            __syncthreads();                                  // E
            if (tid == 0) {
                float sI = 0.f, sR = 0.f;
#pragma unroll
                for (int w = 0; w < 8; ++w) { sI += redI[w]; sR += redR[w]; }
                // K*N = 131072 ; K*K*N = 2097152
                out[0] = alpha[0] * (sI / 131072.0f) - sR / 2097152.0f;
            }
        }
    }
}

extern "C" void kernel_launch(void* const* d_in, const int* in_sizes, int n_in,
                              void* d_out, int out_size) {
    const float* ne    = (const float*)d_in[0];  // (3, 8192, 64) f32
    const float* comm  = (const float*)d_in[1];  // (16, 64) f32
    const float* ricci = (const float*)d_in[2];  // (8192, 8192) f32
    const float* alpha = (const float*)d_in[3];  // scalar f32
    float* out = (float*)d_out;                  // 1 element f32

    stage1<<<N_NODES / 16, 256>>>(ne, comm);
    stage2<<<S2_GRID, 296 == S2_GRID ? 256 : 256>>>(ricci, alpha, out);
}

// round 15
// speedup vs baseline: 1.0806x; 1.0117x over previous
#include <cuda_runtime.h>
#include <cstdint>

#define N_NODES 8192
#define N_COMM 16
#define DIMS 64

#define TILE_ROWS 128
#define TILE_COLS 256
#define N_TILES_R (N_NODES / TILE_ROWS)   // 64
#define N_TILES_C (N_NODES / TILE_COLS)   // 32
#define N_TILES (N_TILES_R * N_TILES_C)   // 2048
#define S2_GRID 740                        // 148 SMs * 5 resident blocks

// Scratch (no device allocation allowed) — fully rewritten every launch.
__device__ float g_pi[N_NODES * N_COMM];
__device__ __align__(16) float g_partI[N_TILES];
__device__ __align__(16) float g_partR[N_TILES];
__device__ int g_ticket;
__device__ int g_done;

// ============================================================================
// Stage 1: distances over 3 manifolds -> dist_norm -> softmax -> g_pi
// (measured ~5us in earlier rounds). Also resets stage2 counters.
// ============================================================================
__global__ __launch_bounds__(256) void stage1(const float* __restrict__ ne,
                                              const float* __restrict__ comm) {
    __shared__ float sC[N_COMM * 68];            // [k][d], row padded to 68
    __shared__ float sX[16][3 * DIMS + 4];       // [node][l*64+d]
    int tid = threadIdx.x;

    if (blockIdx.x == 0 && tid == 0) { g_ticket = 0; g_done = 0; }

    for (int e = tid; e < N_COMM * DIMS; e += 256) {
        int k = e >> 6, d = e & 63;
        sC[k * 68 + d] = comm[e];
    }
    int n0 = blockIdx.x * 16;
#pragma unroll
    for (int l = 0; l < 3; ++l) {
        float4 v = *(const float4*)(ne + ((size_t)l * N_NODES + n0) * DIMS + tid * 4);
        int node = tid >> 4;
        int d = (tid & 15) * 4;
        *(float4*)&sX[node][l * DIMS + d] = v;
    }
    __syncthreads();

    int warp = tid >> 5, lane = tid & 31;
    int half = lane >> 4, k = lane & 15;
    int nl = warp * 2 + half;
    int node = n0 + nl;

    const float4* xE = (const float4*)&sX[nl][0];
    const float4* xL = (const float4*)&sX[nl][DIMS];
    const float4* xS = (const float4*)&sX[nl][2 * DIMS];
    const float4* cB = (const float4*)&sC[k * 68];

    float t0 = sX[nl][DIMS] * sC[k * 68];
    float accE = 0.f, acc1 = 0.f, acc2 = 0.f;
#pragma unroll
    for (int d4 = 0; d4 < DIMS / 4; ++d4) {
        float4 c = cB[d4];
        float4 a0 = xE[d4], a1 = xL[d4], a2 = xS[d4];
        float dx = a0.x - c.x, dy = a0.y - c.y, dz = a0.z - c.z, dw = a0.w - c.w;
        accE = fmaf(dx, dx, accE); accE = fmaf(dy, dy, accE);
        accE = fmaf(dz, dz, accE); accE = fmaf(dw, dw, accE);
        acc1 = fmaf(a1.x, c.x, acc1); acc1 = fmaf(a1.y, c.y, acc1);
        acc1 = fmaf(a1.z, c.z, acc1); acc1 = fmaf(a1.w, c.w, acc1);
        acc2 = fmaf(a2.x, c.x, acc2); acc2 = fmaf(a2.y, c.y, acc2);
        ac2:
        acc2 = fmaf(a2.z, c.z, acc2); acc2 = fmaf(a2.w, c.w, acc2);
    }
    float lip = acc1 - 2.f * t0;
    float arg = fmaxf(-lip, 1.0000001f);         // f32 round of 1+1e-7
    float dl = acoshf(arg);
    float cs = fminf(fmaxf(acc2, -0.9999999f), 0.9999999f);
    float ds = acosf(cs);
    float dn = sqrtf(accE + dl * dl + ds * ds);

    float m = dn;
#pragma unroll
    for (int o = 8; o; o >>= 1) m = fmaxf(m, __shfl_xor_sync(0xffffffffu, m, o, 16));
    float e = expf(dn - m);
    float s = e;
#pragma unroll
    for (int o = 8; o; o >>= 1) s += __shfl_xor_sync(0xffffffffu, s, o, 16);

    g_pi[node * N_COMM + k] = e / s;
}

// ============================================================================
// Stage 2: streaming pass over ricci, work-stealing over 2048 tiles (128x256).
// SCALAR Y-form, no inline asm (R6/R10/R11 lesson: per-op f32x2 asm costs
// ~1 ALU MOV per FMA in marshalling — alu% > fma% in every profile).
//   lane owns ONE j-column: Y[m] += r_ij * pi_i[m]   (16 independent FFMA)
//   pi_i broadcast from smem (4x LDS.128); R via coalesced per-lane LDG.32.
//   accR is FREE: sum_m Y[m] = sum_i r_ij  (softmax rows sum to 1).
//   fold with pi_j from smem (staged coalesced, read stride-17 conflict-free).
// __launch_bounds__(256,5): 51-reg budget, 40 warps/SM — latency fully hidden,
// FMA pipe is the intended ceiling (~60us floor).
// ============================================================================
__global__ __launch_bounds__(256, 5) void stage2(const float* __restrict__ R,
                                                 const float* __restrict__ alpha,
                                                 float* __restrict__ out) {
    __shared__ __align__(16) float sPi[TILE_ROWS * N_COMM];   // 8 KB
    __shared__ float sPj[TILE_COLS * 17];                     // 17 KB, padded
    __shared__ float redI[8], redR[8];
    __shared__ int s_tile;
    __shared__ int s_last;

    int tid = threadIdx.x;
    int warp = tid >> 5, lane = tid & 31;

    for (;;) {
        if (tid == 0) s_tile = atomicAdd(&g_ticket, 1);
        __syncthreads();                                      // A
        int t = s_tile;
        if (t >= N_TILES) break;
        int it = t & (N_TILES_R - 1);                         // row-fastest
        int jt = t >> 6;                                      // tickets share jt
        int i0 = it * TILE_ROWS;
        int jb0 = jt * TILE_COLS;
        int j = jb0 + tid;                                    // lane's column

        // stage pi rows [i0, i0+128) into sPi (coalesced float4)
        {
            const float4* src = (const float4*)(g_pi + (size_t)i0 * N_COMM);
            float4* dst = (float4*)sPi;
#pragma unroll
            for (int e = 0; e < 2; ++e) dst[tid + 256 * e] = src[tid + 256 * e];
        }
        // stage pi cols [jb0, jb0+256) transposed-padded into sPj (coalesced read)
        for (int e = tid; e < TILE_COLS * N_COMM; e += 256) {
            int jj = e >> 4, m = e & 15;
            sPj[jj * 17 + m] = g_pi[(size_t)(jb0 + jj) * N_COMM + m];
        }
        __syncthreads();                                      // B

        const float* __restrict__ Rp = R + (size_t)i0 * N_NODES + j;

        float Y[16];
#pragma unroll
        for (int m = 0; m < 16; ++m) Y[m] = 0.f;

#pragma unroll 2
        for (int i = 0; i < TILE_ROWS; ++i) {
            float r = __ldg(Rp + (size_t)i * N_NODES);        // coalesced LDG.32
            const float4* q = (const float4*)(sPi + i * N_COMM);
            float4 q0 = q[0], q1 = q[1], q2 = q[2], q3 = q[3]; // broadcast LDS.128
            Y[0]  = fmaf(r, q0.x, Y[0]);  Y[1]  = fmaf(r, q0.y, Y[1]);
            Y[2]  = fmaf(r, q0.z, Y[2]);  Y[3]  = fmaf(r, q0.w, Y[3]);
            Y[4]  = fmaf(r, q1.x, Y[4]);  Y[5]  = fmaf(r, q1.y, Y[5]);
            Y[6]  = fmaf(r, q1.z, Y[6]);  Y[7]  = fmaf(r, q1.w, Y[7]);
            Y[8]  = fmaf(r, q2.x, Y[8]);  Y[9]  = fmaf(r, q2.y, Y[9]);
            Y[10] = fmaf(r, q2.z, Y[10]); Y[11] = fmaf(r, q2.w, Y[11]);
            Y[12] = fmaf(r, q3.x, Y[12]); Y[13] = fmaf(r, q3.y, Y[13]);
            Y[14] = fmaf(r, q3.z, Y[14]); Y[15] = fmaf(r, q3.w, Y[15]);
        }

        // fold: aI = Y . pi_j (stride-17 smem, conflict-free); aR = sum_m Y[m]
        float aI = 0.f, aR = 0.f;
        const float* pj = sPj + tid * 17;
#pragma unroll
        for (int m = 0; m < 16; ++m) {
            aI = fmaf(Y[m], pj[m], aI);
            aR += Y[m];                                       // == sum_i r_ij
        }
#pragma unroll
        for (int o = 16; o; o >>= 1) {
            aI += __shfl_xor_sync(0xffffffffu, aI, o);
            aR += __shfl_xor_sync(0xffffffffu, aR, o);
        }
        if (lane == 0) { redI[warp] = aI; redR[warp] = aR; }
        __syncthreads();                                      // C
        if (tid == 0) {
            float sI = 0.f, sR = 0.f;
#pragma unroll
            for (int w = 0; w < 8; ++w) { sI += redI[w]; sR += redR[w]; }
            g_partI[t] = sI;
            g_partR[t] = sR;
            __threadfence();
            int d = atomicAdd(&g_done, 1);
            s_last = (d == N_TILES - 1);
        }
        __syncthreads();                                      // D
        if (s_last) {
            // last block: deterministic fixed-order reduce of all tile partials
            __threadfence();
            const float4* pI = (const float4*)g_partI;
            const float4* pR = (const float4*)g_partR;
            float aI2 = 0.f, aR2 = 0.f;
            for (int b = tid; b < N_TILES / 4; b += 256) {
                float4 vi = pI[b], vr = pR[b];
                aI2 += (vi.x + vi.y) + (vi.z + vi.w);
                aR2 += (vr.x + vr.y) + (vr.z + vr.w);
            }
#pragma unroll
            for (int o = 16; o; o >>= 1) {
                aI2 += __shfl_xor_sync(0xffffffffu, aI2, o);
                aR2 += __shfl_xor_sync(0xffffffffu, aR2, o);
            }
            if (lane == 0) { redI[warp] = aI2; redR[warp] = aR2; }
            __syncthreads();                                  // E
            if (tid == 0) {
                float sI = 0.f, sR = 0.f;
#pragma unroll
                for (int w = 0; w < 8; ++w) { sI += redI[w]; sR += redR[w]; }
                // K*N = 131072 ; K*K*N = 2097152
                out[0] = alpha[0] * (sI / 131072.0f) - sR / 2097152.0f;
            }
        }
    }
}

extern "C" void kernel_launch(void* const* d_in, const int* in_sizes, int n_in,
                              void* d_out, int out_size) {
    const float* ne    = (const float*)d_in[0];  // (3, 8192, 64) f32
    const float* comm  = (const float*)d_in[1];  // (16, 64) f32
    const float* ricci = (const float*)d_in[2];  // (8192, 8192) f32
    const float* alpha = (const float*)d_in[3];  // scalar f32
    float* out = (float*)d_out;                  // 1 element f32

    stage1<<<N_NODES / 16, 256>>>(ne, comm);
    stage2<<<S2_GRID, 256>>>(ricci, alpha, out);
}